// round 3
// baseline (speedup 1.0000x reference)
#include <cuda_runtime.h>
#include <math.h>

#define N_ROWS 48000
#define DIMS   256
#define KCODES 1024
#define GK     64

#define BM 64          // rows per CTA
#define BN 64          // codes per tile
#define DC 64          // d-chunk for cb staging
#define XPITCH 257     // xs row pitch (words), odd -> bank-safe scalar reads
#define DECAYF 0.99f
#define OMDF   0.01f
#define EPSF   1e-5f

// ---------------- scratch (no allocation allowed) ----------------
__device__ float g_shape_sum[KCODES * DIMS];
__device__ float g_shape_cnt[KCODES];
__device__ float g_gain_sum[GK];
__device__ float g_gain_cnt[GK];

__global__ void init_kernel() {
    int i = blockIdx.x * blockDim.x + threadIdx.x;
    if (i < KCODES * DIMS) g_shape_sum[i] = 0.f;
    if (i < KCODES)        g_shape_cnt[i] = 0.f;
    if (i < GK)  { g_gain_sum[i] = 0.f; g_gain_cnt[i] = 0.f; }
}

// ---------------- main: GEMM + argmax + gain quant + quantize + scatter ----
__global__ __launch_bounds__(256) void vq_main(
    const float* __restrict__ x,
    const float* __restrict__ cb,
    const float* __restrict__ gcb,
    float* __restrict__ out_q)
{
    extern __shared__ float sm[];
    float* xs    = sm;                      // [64][257]
    float* cbs   = xs + BM * XPITCH;        // [DC][BN]  (transposed: d-major)
    float* gains = cbs + DC * BN;           // [64]
    float* bval  = gains + GK;              // [64]
    int*   bidx  = (int*)(bval + BM);       // [64]
    float* bscale= (float*)(bidx + BM);     // [64]

    const int tid = threadIdx.x;
    const int row0 = blockIdx.x * BM;
    const int tx = tid & 15;      // code group 0..15
    const int ty = tid >> 4;      // row group 0..15

    // ---- load x tile: 64 rows x 256 d into smem [row][d] ----
    {
        int r  = tid >> 6;              // 0..3
        int d4 = (tid & 63) * 4;        // 0..252
        #pragma unroll
        for (int p = 0; p < 16; p++) {
            int rr = r + p * 4;
            float4 v = *(const float4*)(x + (size_t)(row0 + rr) * DIMS + d4);
            xs[rr * XPITCH + d4 + 0] = v.x;
            xs[rr * XPITCH + d4 + 1] = v.y;
            xs[rr * XPITCH + d4 + 2] = v.z;
            xs[rr * XPITCH + d4 + 3] = v.w;
        }
    }
    if (tid < GK) gains[tid] = gcb[tid];

    float runv[4]; int runi[4];
    #pragma unroll
    for (int i = 0; i < 4; i++) { runv[i] = -3.4e38f; runi[i] = 0; }

    for (int ct = 0; ct < KCODES / BN; ct++) {
        float acc[4][4];
        #pragma unroll
        for (int i = 0; i < 4; i++)
            #pragma unroll
            for (int j = 0; j < 4; j++) acc[i][j] = 0.f;

        for (int dc = 0; dc < DIMS / DC; dc++) {
            __syncthreads();
            // stage cb chunk transposed: cbs[dloc][c], conflict-free stores
            {
                int c  = tid & 63;
                int dg = tid >> 6;          // 0..3
                #pragma unroll
                for (int q = 0; q < 4; q++) {
                    int dloc = dg * 16 + q * 4;
                    float4 v = *(const float4*)(cb + (size_t)(ct * BN + c) * DIMS
                                                + dc * DC + dloc);
                    cbs[(dloc + 0) * BN + c] = v.x;
                    cbs[(dloc + 1) * BN + c] = v.y;
                    cbs[(dloc + 2) * BN + c] = v.z;
                    cbs[(dloc + 3) * BN + c] = v.w;
                }
            }
            __syncthreads();

            const float* xr = xs + (ty * 4) * XPITCH + dc * DC;
            #pragma unroll 4
            for (int dl = 0; dl < DC; dl++) {
                float4 cv = *(const float4*)(cbs + dl * BN + (tx << 2));
                float xv0 = xr[0 * XPITCH + dl];
                float xv1 = xr[1 * XPITCH + dl];
                float xv2 = xr[2 * XPITCH + dl];
                float xv3 = xr[3 * XPITCH + dl];
                acc[0][0] = fmaf(xv0, cv.x, acc[0][0]);
                acc[0][1] = fmaf(xv0, cv.y, acc[0][1]);
                acc[0][2] = fmaf(xv0, cv.z, acc[0][2]);
                acc[0][3] = fmaf(xv0, cv.w, acc[0][3]);
                acc[1][0] = fmaf(xv1, cv.x, acc[1][0]);
                acc[1][1] = fmaf(xv1, cv.y, acc[1][1]);
                acc[1][2] = fmaf(xv1, cv.z, acc[1][2]);
                acc[1][3] = fmaf(xv1, cv.w, acc[1][3]);
                acc[2][0] = fmaf(xv2, cv.x, acc[2][0]);
                acc[2][1] = fmaf(xv2, cv.y, acc[2][1]);
                acc[2][2] = fmaf(xv2, cv.z, acc[2][2]);
                acc[2][3] = fmaf(xv2, cv.w, acc[2][3]);
                acc[3][0] = fmaf(xv3, cv.x, acc[3][0]);
                acc[3][1] = fmaf(xv3, cv.y, acc[3][1]);
                acc[3][2] = fmaf(xv3, cv.z, acc[3][2]);
                acc[3][3] = fmaf(xv3, cv.w, acc[3][3]);
            }
        }

        // per-tile argmax with first-index tie break (matches jnp.argmax)
        #pragma unroll
        for (int i = 0; i < 4; i++) {
            float bv = acc[i][0]; int bj = 0;
            if (acc[i][1] > bv) { bv = acc[i][1]; bj = 1; }
            if (acc[i][2] > bv) { bv = acc[i][2]; bj = 2; }
            if (acc[i][3] > bv) { bv = acc[i][3]; bj = 3; }
            int bc = ct * BN + tx * 4 + bj;
            #pragma unroll
            for (int off = 1; off < 16; off <<= 1) {
                float ov = __shfl_xor_sync(0xffffffffu, bv, off);
                int   oc = __shfl_xor_sync(0xffffffffu, bc, off);
                if (ov > bv || (ov == bv && oc < bc)) { bv = ov; bc = oc; }
            }
            if (bv > runv[i]) { runv[i] = bv; runi[i] = bc; }
        }
    }

    if (tx == 0) {
        #pragma unroll
        for (int i = 0; i < 4; i++) {
            bval[ty * 4 + i] = runv[i];
            bidx[ty * 4 + i] = runi[i];
        }
    }
    __syncthreads();

    // ---- gain quantization + scalar stats (one thread per row) ----
    if (tid < BM) {
        float g = logf(fmaxf(bval[tid], EPSF));   // LOG_GAIN, clip min EPS
        float bd = 3.4e38f; int gi = 0;
        #pragma unroll
        for (int j = 0; j < GK; j++) {
            float d = g - gains[j];
            float d2 = d * d;
            if (d2 < bd) { bd = d2; gi = j; }     // first-min == first argmax of -d2
        }
        atomicAdd(&g_gain_sum[gi], g);
        atomicAdd(&g_gain_cnt[gi], 1.f);
        atomicAdd(&g_shape_cnt[bidx[tid]], 1.f);
        bscale[tid] = expf(gains[gi]);            // exp(gain_q)
    }
    __syncthreads();

    // ---- epilogue: quantize output + shape_sum scatter ----
    for (int r = 0; r < BM; r++) {
        int k = bidx[r];
        float sc = bscale[r];
        float cv = cb[(size_t)k * DIMS + tid];
        out_q[(size_t)(row0 + r) * DIMS + tid] = sc * cv;
        atomicAdd(&g_shape_sum[(size_t)k * DIMS + tid],
                  x[(size_t)(row0 + r) * DIMS + tid]);
    }
}

// ---------------- finalize: EMA updates ----------------
__device__ __forceinline__ float blockSum256(float v, float* red) {
    __syncthreads();
    int lane = threadIdx.x & 31, w = threadIdx.x >> 5;
    #pragma unroll
    for (int o = 16; o; o >>= 1) v += __shfl_xor_sync(0xffffffffu, v, o);
    if (lane == 0) red[w] = v;
    __syncthreads();
    if (w == 0) {
        float t = (lane < 8) ? red[lane] : 0.f;
        #pragma unroll
        for (int o = 4; o; o >>= 1) t += __shfl_xor_sync(0xffffffffu, t, o);
        if (lane == 0) red[0] = t;
    }
    __syncthreads();
    return red[0];
}

__global__ __launch_bounds__(256) void vq_finalize(
    const float* __restrict__ cb,   const float* __restrict__ gcb,
    const float* __restrict__ snum, const float* __restrict__ gnum,
    float* __restrict__ out_shape,  float* __restrict__ out_gain,
    float* __restrict__ out_snum,   float* __restrict__ out_gnum)
{
    __shared__ float red[8];
    int k = blockIdx.x, t = threadIdx.x;

    float s = g_shape_sum[k * DIMS + t];
    float ss = blockSum256(s * s, red);
    float denom = fmaxf(sqrtf(ss), EPSF);             // clip(norm, EPS)
    float upd = cb[k * DIMS + t] * DECAYF + (s / denom) * OMDF;
    float nn = blockSum256(upd * upd, red);
    float n2 = fmaxf(sqrtf(nn), 1e-12f);              // _l2norm clip 1e-12
    out_shape[k * DIMS + t] = upd / n2;

    if (t == 0)
        out_snum[k] = snum[k] * DECAYF + g_shape_cnt[k] * OMDF;

    if (k == 0 && t < GK) {
        float cnt  = g_gain_cnt[t];
        float gnew = g_gain_sum[t] / fmaxf(cnt, EPSF);
        out_gain[t] = gcb[t]  * DECAYF + gnew * OMDF;
        out_gnum[t] = gnum[t] * DECAYF + cnt  * OMDF;
    }
}

// ---------------- launch ----------------
extern "C" void kernel_launch(void* const* d_in, const int* in_sizes, int n_in,
                              void* d_out, int out_size) {
    const float* x    = (const float*)d_in[0];   // (48000, 256)
    const float* cb   = (const float*)d_in[1];   // (1024, 256)
    const float* gcb  = (const float*)d_in[2];   // (64,)
    const float* snum = (const float*)d_in[3];   // (1024,)
    const float* gnum = (const float*)d_in[4];   // (64,)

    float* out       = (float*)d_out;
    float* out_q     = out;                       // 12,288,000
    float* out_shape = out_q + (size_t)N_ROWS * DIMS;   // 262,144
    float* out_gain  = out_shape + KCODES * DIMS;       // 64
    float* out_snum  = out_gain + GK;                   // 1024
    float* out_gnum  = out_snum + KCODES;               // 64

    init_kernel<<<(KCODES * DIMS + 255) / 256, 256>>>();

    size_t smem = (size_t)(BM * XPITCH + DC * BN + GK + BM + BM + BM) * 4;
    cudaFuncSetAttribute(vq_main, cudaFuncAttributeMaxDynamicSharedMemorySize,
                         (int)smem);
    vq_main<<<N_ROWS / BM, 256, smem>>>(x, cb, gcb, out_q);

    vq_finalize<<<KCODES, 256>>>(cb, gcb, snum, gnum,
                                 out_shape, out_gain, out_snum, out_gnum);
}